// round 17
// baseline (speedup 1.0000x reference)
#include <cuda_runtime.h>
#include <cuda_fp16.h>
#include <mma.h>
#include <cstdint>

using namespace nvcuda;

// Problem constants
#define B_DIM      32
#define S_DIM      2048
#define H_DIM      4096
#define R_DIM      64
#define N_ADAPT    16
#define TILE_M     128
#define KC         64                  // K elements per chunk (locked: R8 win)
#define NCHUNK     (H_DIM / KC)        // 64
#define NTHREADS   256

// SMEM (half): row stride 72 halves = 144 B (conflict-free, ldm mult of 8)
#define LDH        72
#define X_STAGE_H  (TILE_M * LDH)                 // 9216 halves = 18432 B
#define W_STAGE_H  (R_DIM * LDH)                  // 4608 halves = 9216 B
#define STAGE_H    (X_STAGE_H + W_STAGE_H)        // 13824 halves
#define STAGE_B    (STAGE_H * 2)                  // 27648 B
#define SMEM_TOTAL (2 * STAGE_B)                  // 55296 B (x2 CTAs = 110592)

// Pre-converted fp16 weights (8 MB static scratch)
__device__ __half g_wh[N_ADAPT * R_DIM * H_DIM];

__device__ __forceinline__ uint32_t smem_u32(const void* p) {
    uint32_t r;
    asm("{ .reg .u64 t; cvta.to.shared.u64 t, %1; cvt.u32.u64 %0, t; }"
        : "=r"(r) : "l"(p));
    return r;
}

// streaming (evict-first) 16B global load: x is single-use
__device__ __forceinline__ float4 ldg_cs128(const float* p) {
    float4 v;
    asm volatile("ld.global.cs.v4.f32 {%0,%1,%2,%3}, [%4];"
                 : "=f"(v.x), "=f"(v.y), "=f"(v.z), "=f"(v.w) : "l"(p));
    return v;
}

// streaming 16B global store: out is single-use
__device__ __forceinline__ void stg_cs128(float* p, float a, float b,
                                          float c, float d) {
    asm volatile("st.global.cs.v4.f32 [%0], {%1,%2,%3,%4};"
                 :: "l"(p), "f"(a), "f"(b), "f"(c), "f"(d) : "memory");
}

__device__ __forceinline__ void sts64(uint32_t addr, uint32_t a, uint32_t b) {
    asm volatile("st.shared.v2.b32 [%0], {%1, %2};"
                 :: "r"(addr), "r"(a), "r"(b));
}

__device__ __forceinline__ void cp_async16(uint32_t dst, const void* src) {
    asm volatile("cp.async.cg.shared.global [%0], [%1], 16;"
                 :: "r"(dst), "l"(src) : "memory");
}
#define CP_COMMIT() asm volatile("cp.async.commit_group;" ::: "memory")
#define CP_WAIT0()  asm volatile("cp.async.wait_group 0;" ::: "memory")

// ---- kernel 1: convert adapter weights f32 -> f16 (RN), MLP-4 streaming ----
__global__ void __launch_bounds__(256, 8)
convert_w_kernel(const float4* __restrict__ w) {
    const int base = blockIdx.x * 1024 + threadIdx.x;
    float4 v[4];
    #pragma unroll
    for (int j = 0; j < 4; j++)
        v[j] = ldg_cs128((const float*)(w + base + j * 256));
    #pragma unroll
    for (int j = 0; j < 4; j++) {
        __half2 h0 = __floats2half2_rn(v[j].x, v[j].y);
        __half2 h1 = __floats2half2_rn(v[j].z, v[j].w);
        uint2 p;
        p.x = *(const uint32_t*)&h0;
        p.y = *(const uint32_t*)&h1;
        ((uint2*)g_wh)[base + j * 256] = p;
    }
}

// ---- kernel 2: gathered GEMM, fp16 HMMA, KC=64, w via cp.async ------------
__global__ void __launch_bounds__(NTHREADS, 2)
multilora_fp16_wasync_kernel(const float* __restrict__ x,
                             const int* __restrict__ adapter_ids,
                             float* __restrict__ out) {
    extern __shared__ __align__(16) __half smem[];
    const uint32_t smem_base = smem_u32(smem);

    const int tid = threadIdx.x;
    const int wid = tid >> 5;

    const int mtile = blockIdx.x;       // 0..15
    const int b     = blockIdx.y;       // 0..31
    const int m0    = mtile * TILE_M;
    const int aid   = __ldg(adapter_ids + b);

    // ---- x producer mapping: 2048 float4 quads / chunk over 256 thr = 8 each
    const float* xg[8];
    uint32_t xoff[8];
    #pragma unroll
    for (int j = 0; j < 8; j++) {
        int i = tid + j * NTHREADS;
        int row = i >> 4, q = i & 15;
        xg[j]   = x + ((size_t)(b * S_DIM + m0 + row)) * H_DIM + q * 4;
        xoff[j] = (uint32_t)((row * LDH + q * 4) * 2);
    }

    // ---- w cp.async mapping: 512 16B-copies / chunk over 256 thr = 2 each
    const __half* whbase = g_wh + (size_t)aid * R_DIM * H_DIM;
    const __half* wg[2];
    uint32_t woff[2];
    #pragma unroll
    for (int j = 0; j < 2; j++) {
        int i = tid + j * NTHREADS;
        int row = i >> 3, seg = i & 7;
        wg[j]   = whbase + (size_t)row * H_DIM + seg * 8;
        woff[j] = (uint32_t)((X_STAGE_H + row * LDH + seg * 8) * 2);
    }

    // ---- consumer mapping: 8 warps, 32x32 warp tiles (4 along M, 2 along N)
    const int wm = wid >> 1;
    const int wn = wid & 1;

    wmma::fragment<wmma::accumulator, 16, 16, 16, float> acc[2][2];
    #pragma unroll
    for (int fi = 0; fi < 2; fi++)
        #pragma unroll
        for (int fj = 0; fj < 2; fj++)
            wmma::fill_fragment(acc[fi][fj], 0.0f);

    // ---- prologue: w(0) into stage 0 via cp.async; x(0) into registers
    #pragma unroll
    for (int j = 0; j < 2; j++)
        cp_async16(smem_base + woff[j], wg[j]);
    CP_COMMIT();

    float4 cur[8];
    #pragma unroll
    for (int j = 0; j < 8; j++)
        cur[j] = ldg_cs128(xg[j]);

    for (int kc = 0; kc < NCHUNK; kc++) {
        const int s = kc & 1;
        const uint32_t sb = smem_base + s * STAGE_B;
        __half* xs = smem + s * STAGE_H;
        __half* ws = xs + X_STAGE_H;

        // x: RN convert + STS.64 (empties cur)
        #pragma unroll
        for (int j = 0; j < 8; j++) {
            __half2 h0 = __floats2half2_rn(cur[j].x, cur[j].y);
            __half2 h1 = __floats2half2_rn(cur[j].z, cur[j].w);
            sts64(sb + xoff[j],
                  *(const uint32_t*)&h0, *(const uint32_t*)&h1);
        }

        // x loads for chunk kc+1 (land during barrier + 4 k-steps below)
        if (kc + 1 < NCHUNK) {
            #pragma unroll
            for (int j = 0; j < 8; j++)
                cur[j] = ldg_cs128(xg[j] + (size_t)(kc + 1) * KC);
        }

        // w(kc) must be resident (only group(kc) can still be pending)
        CP_WAIT0();

        // Barrier: RAW on stage s (x STS + w cp.async visible to all);
        // also proves WMMA(kc-1) done -> stage s^1 writable below.
        __syncthreads();

        // w(kc+1) via cp.async into stage s^1
        if (kc + 1 < NCHUNK) {
            const uint32_t sb1 = smem_base + (s ^ 1) * STAGE_B;
            #pragma unroll
            for (int j = 0; j < 2; j++)
                cp_async16(sb1 + woff[j], wg[j] + (size_t)(kc + 1) * KC);
        }
        CP_COMMIT();

        // compute: 4 k-steps of m16n16k16
        #pragma unroll
        for (int kk = 0; kk < KC; kk += 16) {
            wmma::fragment<wmma::matrix_a, 16, 16, 16, __half,
                           wmma::row_major> af[2];
            wmma::fragment<wmma::matrix_b, 16, 16, 16, __half,
                           wmma::col_major> bf[2];
            #pragma unroll
            for (int fi = 0; fi < 2; fi++)
                wmma::load_matrix_sync(af[fi],
                    xs + (wm * 32 + fi * 16) * LDH + kk, LDH);
            #pragma unroll
            for (int fj = 0; fj < 2; fj++)
                wmma::load_matrix_sync(bf[fj],
                    ws + (wn * 32 + fj * 16) * LDH + kk, LDH);
            #pragma unroll
            for (int fi = 0; fi < 2; fi++)
                #pragma unroll
                for (int fj = 0; fj < 2; fj++)
                    wmma::mma_sync(acc[fi][fj], af[fi], bf[fj], acc[fi][fj]);
        }
    }

    // ---- epilogue: stage acc tile through smem (reuse stage 0) for
    // coalesced streaming stores. Stage reads are done (loop ended).
    __syncthreads();
    float* otile = (float*)smem;        // 128 x 68 f32 = 34816 B < SMEM_TOTAL
    #pragma unroll
    for (int fi = 0; fi < 2; fi++)
        #pragma unroll
        for (int fj = 0; fj < 2; fj++)
            wmma::store_matrix_sync(
                otile + (wm * 32 + fi * 16) * 68 + wn * 32 + fj * 16,
                acc[fi][fj], 68, wmma::mem_row_major);
    __syncthreads();

    float* obase = out + ((size_t)(b * S_DIM + m0)) * R_DIM;
    #pragma unroll
    for (int i = 0; i < 8; i++) {
        int idx = tid + i * NTHREADS;          // 0..2047 float4s, coalesced
        int row = idx >> 4, col = (idx & 15) * 4;
        const float* src = otile + row * 68 + col;
        stg_cs128(obase + idx * 4, src[0], src[1], src[2], src[3]);
    }
}

extern "C" void kernel_launch(void* const* d_in, const int* in_sizes, int n_in,
                              void* d_out, int out_size) {
    const float* x   = (const float*)d_in[0];
    const int*   ids = (const int*)d_in[1];
    const float* w   = (const float*)d_in[2];
    float* out = (float*)d_out;

    const int b = in_sizes[1];   // number of requests (32)

    // 1) convert adapter weights f32 -> f16 (MLP-4 streaming, ~4.3 us)
    const int n4 = (N_ADAPT * R_DIM * H_DIM) / 4;    // 1,048,576 float4s
    convert_w_kernel<<<n4 / 1024, 256>>>((const float4*)w);

    // 2) main gathered GEMM
    cudaFuncSetAttribute(multilora_fp16_wasync_kernel,
                         cudaFuncAttributeMaxDynamicSharedMemorySize, SMEM_TOTAL);
    dim3 grid(S_DIM / TILE_M, b);
    multilora_fp16_wasync_kernel<<<grid, NTHREADS, SMEM_TOTAL>>>(x, ids, out);
}